// round 2
// baseline (speedup 1.0000x reference)
#include <cuda_runtime.h>
#include <math.h>
#include <float.h>
#include <stdint.h>

// Problem constants (fixed by the reference)
#define B_IMG  32
#define D_DIM  256
#define HW_SZ  4096     // H*W = 64*64
#define K_CB   512
#define NCLS   10
#define NSHR   10

// Tiling
#define TP     256      // pixels per block
#define KT     56       // padded candidate codes (8 ty-groups x 7)
#define CBS    257      // smem codebook row stride (odd -> conflict-free gather)
#define NTHR   256

#define F32_INF __int_as_float(0x7f800000)

struct ClassRanges { int lo[NCLS]; int cnt[NCLS]; };

typedef unsigned long long ull;

// ---- packed f32x2 helpers (Blackwell): exact per-lane IEEE fp32 semantics --
__device__ __forceinline__ ull pack2(float x) {
    unsigned int b = __float_as_uint(x);
    ull r;
    asm("mov.b64 %0, {%1, %1};" : "=l"(r) : "r"(b));
    return r;
}
// fused multiply-add per lane (same bits as scalar fmaf)
__device__ __forceinline__ void fma2(ull& d, ull a, ull b) {
    asm("fma.rn.f32x2 %0, %1, %2, %0;" : "+l"(d) : "l"(a), "l"(b));
}
// rounded multiply per lane (same bits as scalar __fmul_rn) — NOT fused
__device__ __forceinline__ ull mul2(ull a, ull b) {
    ull r;
    asm("mul.rn.f32x2 %0, %1, %2;" : "=l"(r) : "l"(a), "l"(b));
    return r;
}
// rounded add per lane (same bits as scalar __fadd_rn)
__device__ __forceinline__ void add2(ull& d, ull a) {
    asm("add.rn.f32x2 %0, %0, %1;" : "+l"(d) : "l"(a));
}
__device__ __forceinline__ float2 unpack2(ull v) {
    unsigned int lo, hi;
    asm("mov.b64 {%0, %1}, %2;" : "=r"(lo), "=r"(hi) : "l"(v));
    return make_float2(__uint_as_float(lo), __uint_as_float(hi));
}

// ----------------------------------------------------------------------------
// One block: image b, 256 contiguous pixels. Candidate codes = contiguous
// codebook slice [lo, lo+cnt) for this image's class, resident in smem.
//
// Replicates the reference's fp32 arithmetic:
//   A   = in_sqr  : sequential ascending sum of fl(x_d*x_d)   (mul then add)
//   g_k = x . c_k : sequential ascending fused-FMA chain (Eigen gebp order)
//   p_k = ||c_k||^2 (fine accuracy only; order non-critical)
//   d_k = fl( fl(A + p_k) - 2*g_k );  argmin, first-min tie-break.
// ----------------------------------------------------------------------------
__global__ void __launch_bounds__(NTHR, 1)
vq_kernel(const float* __restrict__ z, const float* __restrict__ cb,
          const int* __restrict__ labels, float* __restrict__ out,
          ClassRanges cr)
{
    extern __shared__ float smem[];
    float* cb_s = smem;                 // [KT][CBS]
    float* p_s  = smem + KT * CBS;      // [64]  cb_sqr (+inf for padded rows)
    float* x_s  = p_s + 64;             // [64][256] d-chunk of x, reused later

    const int tid = threadIdx.x;
    const int tx  = tid & 31;           // pixel-pair lane
    const int ty  = tid >> 5;           // code group (0..7)
    const int b   = blockIdx.y;
    const int hw0 = blockIdx.x * TP;

    const int label = labels[b];
    const int lo    = cr.lo[label];
    const int cnt   = cr.cnt[label];    // 50 or 51

    // ---- load codebook slice (padded rows = 0) ----
    for (int i = tid; i < KT * D_DIM; i += NTHR) {
        const int kk = i >> 8;
        const int d  = i & 255;
        float v = 0.0f;
        if (kk < cnt) v = cb[(size_t)(lo + kk) * D_DIM + d];
        cb_s[kk * CBS + d] = v;
    }
    __syncthreads();

    // ---- cb_sqr per row: rounded mul + add (order non-critical: err ~1e-11,
    //      vs ulp(256)=3e-5 decision grid) ----
    #pragma unroll
    for (int j = 0; j < 7; ++j) {
        const int kk = ty * 7 + j;
        float s = 0.0f;
        #pragma unroll
        for (int d = tx; d < D_DIM; d += 32) {
            const float v = cb_s[kk * CBS + d];
            s = __fadd_rn(s, __fmul_rn(v, v));
        }
        #pragma unroll
        for (int o = 16; o > 0; o >>= 1)
            s = __fadd_rn(s, __shfl_xor_sync(0xffffffffu, s, o));
        if (tx == 0)
            p_s[kk] = (kk < cnt) ? s : F32_INF;
    }
    __syncthreads();

    // ---- main pass: g (ascending fused-FMA) and A (ascending mul+add), with
    //      8 pixels (4 f32x2 pairs) x 7 codes per thread ----
    ull acc[7][4];      // g chains
    ull asq[4];         // in_sqr chains (per pixel pair)
    #pragma unroll
    for (int j = 0; j < 7; ++j)
        #pragma unroll
        for (int r = 0; r < 4; ++r) acc[j][r] = 0ULL;
    #pragma unroll
    for (int r = 0; r < 4; ++r) asq[r] = 0ULL;

    const float* xbase = z + (size_t)b * D_DIM * HW_SZ + hw0;

    for (int ch = 0; ch < 4; ++ch) {
        const int dc0 = ch << 6;
        const float* xs = xbase + (size_t)dc0 * HW_SZ;
        // stage x chunk [64 d][256 px] into smem (float4, coalesced)
        for (int i = tid; i < 64 * 64; i += NTHR) {
            const int row = i >> 6;
            const int c4  = (i & 63) << 2;
            *(float4*)&x_s[(row << 8) + c4] =
                *(const float4*)(xs + (size_t)row * HW_SZ + c4);
        }
        __syncthreads();

        #pragma unroll 2
        for (int dd = 0; dd < 64; ++dd) {
            ull xp[4];
            #pragma unroll
            for (int r = 0; r < 4; ++r)
                xp[r] = *(const ull*)&x_s[(dd << 8) + (tx << 1) + (r << 6)];
            // in_sqr: rounded square then rounded add (sequential in d)
            #pragma unroll
            for (int r = 0; r < 4; ++r) add2(asq[r], mul2(xp[r], xp[r]));
            #pragma unroll
            for (int j = 0; j < 7; ++j) {
                const float cv = cb_s[(ty * 7 + j) * CBS + dc0 + dd]; // bcast
                const ull c2 = pack2(cv);
                #pragma unroll
                for (int r = 0; r < 4; ++r) fma2(acc[j][r], xp[r], c2);
            }
        }
        __syncthreads();
    }

    // ---- distances d = fl(fl(A + p) - 2g); per-thread first-min argmin ----
    float* rs   = x_s;                      // [8][256] best distance
    int*   ri   = (int*)(x_s + 8 * 256);    // [8][256] slice indices
    int*   best = (int*)(x_s + 16 * 256);   // [256]

    #pragma unroll
    for (int r = 0; r < 4; ++r) {
        const float2 Av = unpack2(asq[r]);
        float bd0 = F32_INF, bd1 = F32_INF;
        int   bi0 = 0,       bi1 = 0;
        #pragma unroll
        for (int j = 0; j < 7; ++j) {
            const int kk = ty * 7 + j;
            const float p = p_s[kk];
            const float2 g = unpack2(acc[j][r]);
            const float d0 = __fadd_rn(__fadd_rn(Av.x, p), -(2.0f * g.x));
            const float d1 = __fadd_rn(__fadd_rn(Av.y, p), -(2.0f * g.y));
            if (d0 < bd0) { bd0 = d0; bi0 = kk; }   // strict < keeps lowest idx
            if (d1 < bd1) { bd1 = d1; bi1 = kk; }
        }
        const int p0 = (tx << 1) + (r << 6);
        rs[ty * 256 + p0]     = bd0;  ri[ty * 256 + p0]     = bi0;
        rs[ty * 256 + p0 + 1] = bd1;  ri[ty * 256 + p0 + 1] = bi1;
    }
    __syncthreads();

    {
        float bd = rs[tid];
        int   bi = ri[tid];
        #pragma unroll
        for (int t2 = 1; t2 < 8; ++t2) {
            const float s = rs[t2 * 256 + tid];
            if (s < bd) { bd = s; bi = ri[t2 * 256 + tid]; } // idx ascends w/ ty
        }
        best[tid] = bi;
    }
    __syncthreads();

    // ---- epilogue: z_q_x = fl(x + fl(codes - x)) (exact reference replication),
    //      z_q_x_bar = codes. float4-coalesced over pixels. ----
    const size_t obase = (size_t)b * D_DIM * HW_SZ + hw0;
    const float* zsrc  = z + obase;
    float* o0 = out + obase;
    float* o1 = out + (size_t)B_IMG * D_DIM * HW_SZ + obase;

    const int px0 = (tid & 63) << 2;
    const int d0  = tid >> 6;
    const float* c0 = cb_s + best[px0 + 0] * CBS;
    const float* c1 = cb_s + best[px0 + 1] * CBS;
    const float* c2 = cb_s + best[px0 + 2] * CBS;
    const float* c3 = cb_s + best[px0 + 3] * CBS;

    #pragma unroll 4
    for (int d = d0; d < D_DIM; d += 4) {
        const size_t off = (size_t)d * HW_SZ + px0;
        const float4 xv = *(const float4*)(zsrc + off);
        float4 cv;
        cv.x = c0[d]; cv.y = c1[d]; cv.z = c2[d]; cv.w = c3[d];
        float4 q;
        q.x = __fadd_rn(xv.x, __fadd_rn(cv.x, -xv.x));
        q.y = __fadd_rn(xv.y, __fadd_rn(cv.y, -xv.y));
        q.z = __fadd_rn(xv.z, __fadd_rn(cv.z, -xv.z));
        q.w = __fadd_rn(xv.w, __fadd_rn(cv.w, -xv.w));
        *(float4*)(o0 + off) = q;
        *(float4*)(o1 + off) = cv;
    }
}

extern "C" void kernel_launch(void* const* d_in, const int* in_sizes, int n_in,
                              void* d_out, int out_size)
{
    const float* z      = (const float*)d_in[0];
    const float* cb     = (const float*)d_in[1];
    const int*   labels = (const int*)d_in[2];
    float*       out    = (float*)d_out;
    (void)in_sizes; (void)n_in; (void)out_size;

    // Class -> contiguous codebook range, replicating
    // round(linspace(-0.5, NCLS-0.51, K-NSHR)). Boundary margins ~1e-3 in
    // value space vs ~1e-6 fp error, so double + nearbyint is exact.
    ClassRanges cr;
    for (int c = 0; c < NCLS; ++c) { cr.lo[c] = 0; cr.cnt[c] = 0; }
    const double step = (((double)NCLS - 0.51) + 0.5) / (double)(K_CB - NSHR - 1);
    int prev = -1;
    for (int i = 0; i < K_CB - NSHR; ++i) {
        const double v = -0.5 + (double)i * step;
        int c = (int)nearbyint(v);            // round-half-even, like jnp.round
        if (c < 0) c = 0;
        if (c > NCLS - 1) c = NCLS - 1;
        if (c != prev) { cr.lo[c] = i; prev = c; }
        cr.cnt[c] += 1;
    }

    const size_t smem_bytes = (size_t)(KT * CBS + 64 + 64 * 256) * sizeof(float);
    cudaFuncSetAttribute(vq_kernel,
                         cudaFuncAttributeMaxDynamicSharedMemorySize,
                         (int)smem_bytes);

    dim3 grid(HW_SZ / TP, B_IMG);
    vq_kernel<<<grid, NTHR, smem_bytes>>>(z, cb, labels, out, cr);
}

// round 3
// speedup vs baseline: 1.3705x; 1.3705x over previous
#include <cuda_runtime.h>
#include <math.h>
#include <float.h>
#include <stdint.h>

// Problem constants (fixed by the reference)
#define B_IMG  32
#define D_DIM  256
#define HW_SZ  4096     // H*W = 64*64
#define K_CB   512
#define NCLS   10
#define NSHR   10

// Tiling
#define TP     256      // pixels per block
#define KT     56       // padded candidate codes (8 ty-groups x 7)
#define CBS2   258      // smem codebook row stride (EVEN: allows LDS.64 pairs;
                        //  bank start = 2k mod 32 -> epilogue gather mostly ok)
#define CHROWS 32       // d-rows staged per chunk
#define NCHNK  (D_DIM / CHROWS)
#define NTHR   256

#define F32_INF __int_as_float(0x7f800000)

struct ClassRanges { int lo[NCLS]; int cnt[NCLS]; };

typedef unsigned long long ull;

// ---- packed f32x2 helpers (Blackwell): exact per-lane IEEE fp32 semantics --
__device__ __forceinline__ ull pack2(float x) {
    unsigned int b = __float_as_uint(x);
    ull r;
    asm("mov.b64 %0, {%1, %1};" : "=l"(r) : "r"(b));
    return r;
}
__device__ __forceinline__ void fma2(ull& d, ull a, ull b) {
    asm("fma.rn.f32x2 %0, %1, %2, %0;" : "+l"(d) : "l"(a), "l"(b));
}
__device__ __forceinline__ float2 unpack2(ull v) {
    unsigned int lo, hi;
    asm("mov.b64 {%0, %1}, %2;" : "=r"(lo), "=r"(hi) : "l"(v));
    return make_float2(__uint_as_float(lo), __uint_as_float(hi));
}

// ----------------------------------------------------------------------------
// One block: image b, 256 contiguous pixels. Candidate codes = contiguous
// codebook slice [lo, lo+cnt) for this image's class, resident in smem.
//
// Bit-exact replication of the reference fp32 arithmetic (validated round 2):
//   A   = in_sqr  : sequential ascending sum of fl(x_d*x_d)  (mul then add)
//   g_k = x . c_k : sequential ascending fused-FMA chain
//   p_k = ||c_k||^2 (order non-critical: err ~1e-11 vs ulp(256)=3e-5 grid)
//   d_k = fl( fl(A + p_k) - 2*g_k );  argmin, first-min tie-break.
// ----------------------------------------------------------------------------
__global__ void __launch_bounds__(NTHR, 2)
vq_kernel(const float* __restrict__ z, const float* __restrict__ cb,
          const int* __restrict__ labels, float* __restrict__ out,
          ClassRanges cr)
{
    extern __shared__ float smem[];
    float* cb_s = smem;                       // [KT][CBS2]
    float* p_s  = cb_s + KT * CBS2;           // [64]  cb_sqr (+inf pads)
    float* A_s  = p_s + 64;                   // [256] in_sqr per pixel
    float* x_s  = A_s + 256;                  // [CHROWS][256], reused later

    const int tid = threadIdx.x;
    const int tx  = tid & 31;                 // pixel-pair lane
    const int ty  = tid >> 5;                 // code group (0..7)
    const int b   = blockIdx.y;
    const int hw0 = blockIdx.x * TP;

    const int label = labels[b];
    const int lo    = cr.lo[label];
    const int cnt   = cr.cnt[label];          // 50 or 51

    // ---- load codebook slice (padded rows = 0), float2-vectorized ----
    for (int i = tid; i < KT * (D_DIM / 2); i += NTHR) {
        const int kk = i >> 7;                // 128 float2 per row
        const int d2 = (i & 127) << 1;
        float2 v = make_float2(0.0f, 0.0f);
        if (kk < cnt) v = *(const float2*)(cb + (size_t)(lo + kk) * D_DIM + d2);
        *(float2*)&cb_s[kk * CBS2 + d2] = v;
    }
    __syncthreads();

    // ---- cb_sqr per row (bank-conflict-free: addr = 2kk + tx mod 32) ----
    #pragma unroll
    for (int j = 0; j < 7; ++j) {
        const int kk = ty * 7 + j;
        float s = 0.0f;
        #pragma unroll
        for (int d = tx; d < D_DIM; d += 32) {
            const float v = cb_s[kk * CBS2 + d];
            s = __fadd_rn(s, __fmul_rn(v, v));
        }
        #pragma unroll
        for (int o = 16; o > 0; o >>= 1)
            s = __fadd_rn(s, __shfl_xor_sync(0xffffffffu, s, o));
        if (tx == 0)
            p_s[kk] = (kk < cnt) ? s : F32_INF;
    }

    // ---- main pass over 8 chunks of 32 d-rows ----
    ull acc[7][4];                            // g chains: 7 codes x 4 px-pairs
    #pragma unroll
    for (int j = 0; j < 7; ++j)
        #pragma unroll
        for (int r = 0; r < 4; ++r) acc[j][r] = 0ULL;
    float Aacc = 0.0f;                        // in_sqr chain for pixel == tid

    const float* xbase = z + (size_t)b * D_DIM * HW_SZ + hw0;

    for (int ch = 0; ch < NCHNK; ++ch) {
        const int dc0 = ch * CHROWS;
        const float* xs = xbase + (size_t)dc0 * HW_SZ;
        __syncthreads();                       // protect x_s reuse
        // stage x chunk [32 d][256 px] (float4, coalesced; 8 per thread)
        for (int i = tid; i < CHROWS * 64; i += NTHR) {
            const int row = i >> 6;
            const int c4  = (i & 63) << 2;
            *(float4*)&x_s[(row << 8) + c4] =
                *(const float4*)(xs + (size_t)row * HW_SZ + c4);
        }
        __syncthreads();

        // in_sqr pass: thread owns pixel tid, ascending d (bit-exact order)
        #pragma unroll
        for (int dd = 0; dd < CHROWS; ++dd) {
            const float v = x_s[(dd << 8) + tid];
            Aacc = __fadd_rn(Aacc, __fmul_rn(v, v));
        }

        // GEMM: 2 d per iteration; code values fetched as float2 (LDS.64)
        #pragma unroll 1
        for (int dd = 0; dd < CHROWS; dd += 2) {
            float2 cp[7];
            #pragma unroll
            for (int j = 0; j < 7; ++j)
                cp[j] = *(const float2*)&cb_s[(ty * 7 + j) * CBS2 + dc0 + dd];

            ull xp[4];
            #pragma unroll
            for (int r = 0; r < 4; ++r)
                xp[r] = *(const ull*)&x_s[(dd << 8) + (tx << 1) + (r << 6)];
            #pragma unroll
            for (int j = 0; j < 7; ++j) {
                const ull c2 = pack2(cp[j].x);
                #pragma unroll
                for (int r = 0; r < 4; ++r) fma2(acc[j][r], xp[r], c2);
            }
            #pragma unroll
            for (int r = 0; r < 4; ++r)
                xp[r] = *(const ull*)&x_s[((dd + 1) << 8) + (tx << 1) + (r << 6)];
            #pragma unroll
            for (int j = 0; j < 7; ++j) {
                const ull c2 = pack2(cp[j].y);
                #pragma unroll
                for (int r = 0; r < 4; ++r) fma2(acc[j][r], xp[r], c2);
            }
        }
    }
    A_s[tid] = Aacc;
    __syncthreads();

    // ---- distances d = fl(fl(A + p) - 2g); per-thread first-min argmin ----
    float* rs   = x_s;                        // [8][256] best distance
    int*   ri   = (int*)(x_s + 8 * 256);      // [8][256] slice indices
    int*   best = (int*)(x_s + 16 * 256);     // [256]  (fits in 32KB region? 17KB yes)

    #pragma unroll
    for (int r = 0; r < 4; ++r) {
        const int p0 = (tx << 1) + (r << 6);
        const float2 Av = *(const float2*)&A_s[p0];
        float bd0 = F32_INF, bd1 = F32_INF;
        int   bi0 = 0,       bi1 = 0;
        #pragma unroll
        for (int j = 0; j < 7; ++j) {
            const int kk = ty * 7 + j;
            const float p = p_s[kk];
            const float2 g = unpack2(acc[j][r]);
            const float d0 = __fadd_rn(__fadd_rn(Av.x, p), -(2.0f * g.x));
            const float d1 = __fadd_rn(__fadd_rn(Av.y, p), -(2.0f * g.y));
            if (d0 < bd0) { bd0 = d0; bi0 = kk; }  // strict < keeps lowest idx
            if (d1 < bd1) { bd1 = d1; bi1 = kk; }
        }
        rs[ty * 256 + p0]     = bd0;  ri[ty * 256 + p0]     = bi0;
        rs[ty * 256 + p0 + 1] = bd1;  ri[ty * 256 + p0 + 1] = bi1;
    }
    __syncthreads();

    {
        float bd = rs[tid];
        int   bi = ri[tid];
        #pragma unroll
        for (int t2 = 1; t2 < 8; ++t2) {
            const float s = rs[t2 * 256 + tid];
            if (s < bd) { bd = s; bi = ri[t2 * 256 + tid]; } // idx ascends w/ ty
        }
        best[tid] = bi;
    }
    __syncthreads();

    // ---- epilogue: z_q_x = fl(x + fl(codes - x)), z_q_x_bar = codes ----
    const size_t obase = (size_t)b * D_DIM * HW_SZ + hw0;
    const float* zsrc  = z + obase;
    float* o0 = out + obase;
    float* o1 = out + (size_t)B_IMG * D_DIM * HW_SZ + obase;

    const int px0 = (tid & 63) << 2;
    const int d0  = tid >> 6;
    const float* c0 = cb_s + best[px0 + 0] * CBS2;
    const float* c1 = cb_s + best[px0 + 1] * CBS2;
    const float* c2 = cb_s + best[px0 + 2] * CBS2;
    const float* c3 = cb_s + best[px0 + 3] * CBS2;

    #pragma unroll 4
    for (int d = d0; d < D_DIM; d += 4) {
        const size_t off = (size_t)d * HW_SZ + px0;
        const float4 xv = *(const float4*)(zsrc + off);
        float4 cv;
        cv.x = c0[d]; cv.y = c1[d]; cv.z = c2[d]; cv.w = c3[d];
        float4 q;
        q.x = __fadd_rn(xv.x, __fadd_rn(cv.x, -xv.x));
        q.y = __fadd_rn(xv.y, __fadd_rn(cv.y, -xv.y));
        q.z = __fadd_rn(xv.z, __fadd_rn(cv.z, -xv.z));
        q.w = __fadd_rn(xv.w, __fadd_rn(cv.w, -xv.w));
        *(float4*)(o0 + off) = q;
        *(float4*)(o1 + off) = cv;
    }
}

extern "C" void kernel_launch(void* const* d_in, const int* in_sizes, int n_in,
                              void* d_out, int out_size)
{
    const float* z      = (const float*)d_in[0];
    const float* cb     = (const float*)d_in[1];
    const int*   labels = (const int*)d_in[2];
    float*       out    = (float*)d_out;
    (void)in_sizes; (void)n_in; (void)out_size;

    // Class -> contiguous codebook range, replicating
    // round(linspace(-0.5, NCLS-0.51, K-NSHR)) exactly (double + half-even).
    ClassRanges cr;
    for (int c = 0; c < NCLS; ++c) { cr.lo[c] = 0; cr.cnt[c] = 0; }
    const double step = (((double)NCLS - 0.51) + 0.5) / (double)(K_CB - NSHR - 1);
    int prev = -1;
    for (int i = 0; i < K_CB - NSHR; ++i) {
        const double v = -0.5 + (double)i * step;
        int c = (int)nearbyint(v);
        if (c < 0) c = 0;
        if (c > NCLS - 1) c = NCLS - 1;
        if (c != prev) { cr.lo[c] = i; prev = c; }
        cr.cnt[c] += 1;
    }

    const size_t smem_bytes =
        (size_t)(KT * CBS2 + 64 + 256 + CHROWS * 256) * sizeof(float);
    cudaFuncSetAttribute(vq_kernel,
                         cudaFuncAttributeMaxDynamicSharedMemorySize,
                         (int)smem_bytes);

    dim3 grid(HW_SZ / TP, B_IMG);
    vq_kernel<<<grid, NTHR, smem_bytes>>>(z, cb, labels, out, cr);
}